// round 1
// baseline (speedup 1.0000x reference)
#include <cuda_runtime.h>

#define CUTOFF 8.0f
#define MAXK 32
#define MAXE (1 << 20)

// Per-interval spline coefficients (a,b,c,d) for the radial (f) and angular (g) splines.
__device__ float4 g_fc[MAXK];
__device__ float4 g_gc[MAXK];
__device__ int    g_deg;
// Per-edge precompute: (ux, uy, uz, f(|r|)) where u = r/|r|.
__device__ float4 g_edge[MAXE];

// ---------------------------------------------------------------------------
// Kernel 1: single thread. Derive deg from dst, build natural-cubic spline
// coefficients for both splines (uniform knots -> Thomas on K-2 unknowns).
// ---------------------------------------------------------------------------
__device__ void build_spline(const float* y, int K, float h, float4* out) {
    // dy_i = (y[i+1]-y[i])/h
    double dy[MAXK];
    for (int i = 0; i < K - 1; i++) dy[i] = ((double)y[i + 1] - (double)y[i]) / (double)h;

    int n = K - 2;                 // interior second-derivative unknowns
    double M[MAXK];                // M[0..K-1], natural BC: M[0]=M[K-1]=0
    for (int i = 0; i < K; i++) M[i] = 0.0;

    if (n > 0) {
        // Tridiagonal: main = 4h, off = h, rhs_i = 6*(dy[i+1]-dy[i])
        double cp[MAXK], dp[MAXK];
        double hh = (double)h;
        double b0 = 4.0 * hh;
        cp[0] = hh / b0;
        dp[0] = 6.0 * (dy[1] - dy[0]) / b0;
        for (int i = 1; i < n; i++) {
            double denom = 4.0 * hh - hh * cp[i - 1];
            cp[i] = hh / denom;
            dp[i] = (6.0 * (dy[i + 1] - dy[i]) - hh * dp[i - 1]) / denom;
        }
        double x = dp[n - 1];
        M[n] = x;                  // M[i+1] = m_i ; last interior index is n
        for (int i = n - 2; i >= 0; i--) {
            x = dp[i] - cp[i] * x;
            M[i + 1] = x;
        }
    }

    for (int i = 0; i < K - 1; i++) {
        float a = y[i];
        float b = (float)(dy[i] - (double)h * (2.0 * M[i] + M[i + 1]) / 6.0);
        float c = (float)(M[i] / 2.0);
        float d = (float)((M[i + 1] - M[i]) / (6.0 * (double)h));
        out[i] = make_float4(a, b, c, d);
    }
}

__global__ void smeam_build_kernel(const float* __restrict__ fy,
                                   const float* __restrict__ gy,
                                   const int* __restrict__ dst,
                                   int E, int K) {
    // dst = repeat(arange(N), deg) -> N = dst[E-1]+1, deg = E/N
    int N = dst[E - 1] + 1;
    g_deg = E / N;
    build_spline(fy, K, CUTOFF / (float)(K - 1), g_fc);
    build_spline(gy, K, 2.0f / (float)(K - 1), g_gc);
}

// ---------------------------------------------------------------------------
// Kernel 2: per-edge precompute. u = r/|r|, fval = f_spline(|r|).
// ---------------------------------------------------------------------------
__global__ void smeam_edge_kernel(const float* __restrict__ r, int E, int K) {
    int i = blockIdx.x * blockDim.x + threadIdx.x;
    if (i >= E) return;
    float x = r[3 * i + 0];
    float y = r[3 * i + 1];
    float z = r[3 * i + 2];
    float d2 = x * x + y * y + z * z;
    float invl = rsqrtf(d2);
    float l = d2 * invl;  // |r|

    float hf = CUTOFF / (float)(K - 1);
    float inv_hf = (float)(K - 1) / CUTOFF;
    int idx = (int)floorf(l * inv_hf);
    idx = min(max(idx, 0), K - 2);
    float s = l - (float)idx * hf;
    float4 cf = g_fc[idx];
    float fv = cf.x + s * (cf.y + s * (cf.z + s * cf.w));

    g_edge[i] = make_float4(x * invl, y * invl, z * invl, fv);
}

// ---------------------------------------------------------------------------
// Kernel 3: one warp per output edge e2. Lane j handles triplet partner
// e1 = src[e2]*deg + j (contiguous -> coalesced float4 loads, L2-resident).
// ---------------------------------------------------------------------------
__global__ void smeam_main_kernel(const int* __restrict__ src,
                                  const int* __restrict__ dst,
                                  float* __restrict__ out,
                                  int E, int K) {
    __shared__ float4 sg[MAXK];
    if (threadIdx.x < K - 1) sg[threadIdx.x] = g_gc[threadIdx.x];
    __syncthreads();

    int warp = (blockIdx.x * blockDim.x + threadIdx.x) >> 5;
    int lane = threadIdx.x & 31;
    if (warp >= E) return;

    int e2 = warp;
    float4 u2 = g_edge[e2];   // broadcast load (all lanes same addr)
    int s2 = src[e2];
    int d2 = dst[e2];
    int deg = g_deg;
    long base = (long)s2 * (long)deg;

    float hg = 2.0f / (float)(K - 1);
    float inv_hg = (float)(K - 1) * 0.5f;

    float acc = 0.0f;
    for (int j = lane; j < deg; j += 32) {
        long e1 = base + j;
        float4 u1 = g_edge[e1];
        int s1 = src[e1];
        // cos = dot(-r1, r2)/(l1*l2) = -dot(u1, u2)
        float c = -(u1.x * u2.x + u1.y * u2.y + u1.z * u2.z);
        c = fminf(fmaxf(c, -1.0f), 1.0f);
        float xc = c + 1.0f;                      // offset from knot t0=-1
        int idx = (int)floorf(xc * inv_hg);
        idx = min(max(idx, 0), K - 2);
        float s = xc - (float)idx * hg;
        float4 cf = sg[idx];
        float gv = cf.x + s * (cf.y + s * (cf.z + s * cf.w));
        float m = u1.w * u2.w * gv;
        acc += (s1 != d2) ? m : 0.0f;
    }

    // warp reduce
    #pragma unroll
    for (int o = 16; o; o >>= 1) acc += __shfl_down_sync(0xffffffffu, acc, o);
    if (lane == 0) out[e2] = acc;
}

// ---------------------------------------------------------------------------
extern "C" void kernel_launch(void* const* d_in, const int* in_sizes, int n_in,
                              void* d_out, int out_size) {
    const float* r   = (const float*)d_in[0];
    const float* fy  = (const float*)d_in[1];
    const float* gy  = (const float*)d_in[2];
    const int*   src = (const int*)d_in[3];
    const int*   dst = (const int*)d_in[4];
    float*       out = (float*)d_out;

    int E = in_sizes[3];   // src has E elements
    int K = in_sizes[1];   // f_coeffs has K elements

    smeam_build_kernel<<<1, 1>>>(fy, gy, dst, E, K);

    int t2 = 256;
    smeam_edge_kernel<<<(E + t2 - 1) / t2, t2>>>(r, E, K);

    int t3 = 256;
    long total = (long)E * 32;  // one warp per e2
    unsigned blocks = (unsigned)((total + t3 - 1) / t3);
    smeam_main_kernel<<<blocks, t3>>>(src, dst, out, E, K);
}

// round 2
// speedup vs baseline: 2.2321x; 2.2321x over previous
#include <cuda_runtime.h>

#define CUTOFF 8.0f
#define MAXK 32
#define MAXE (1 << 20)

// Per-edge precompute: (ux, uy, uz, f(|r|)) where u = r/|r|.
__device__ float4 g_edge[MAXE];
// Fallback-path coefficient storage (generic K only).
__device__ float4 g_fc[MAXK];
__device__ float4 g_gc[MAXK];
__device__ int    g_deg;

// ===========================================================================
// Compile-time-K natural cubic spline (uniform knots). All-register Thomas.
// Writes K-1 per-interval (a,b,c,d) float4s to sh_out (shared).
// ===========================================================================
template <int K>
__device__ __forceinline__ void build_spline_reg(const float* __restrict__ y,
                                                 float h, float4* sh_out) {
    float yv[K];
#pragma unroll
    for (int i = 0; i < K; i++) yv[i] = y[i];

    const float inv_h = 1.0f / h;
    float dy[K - 1];
#pragma unroll
    for (int i = 0; i < K - 1; i++) dy[i] = (yv[i + 1] - yv[i]) * inv_h;

    // Interior unknowns M[1..K-2]; natural BC M[0]=M[K-1]=0.
    // Row-normalized system: 1*M[i-1] + 4*M[i] + 1*M[i+1] = 6*(dy[i]-dy[i-1])/h
    constexpr int n = K - 2;
    float M[K];
    M[0] = 0.0f;
    M[K - 1] = 0.0f;
    if (n > 0) {
        float cp[n], dp[n];
        cp[0] = 0.25f;
        dp[0] = 6.0f * (dy[1] - dy[0]) * inv_h * 0.25f;
#pragma unroll
        for (int i = 1; i < n; i++) {
            float rd = 1.0f / (4.0f - cp[i - 1]);
            cp[i] = rd;
            dp[i] = (6.0f * (dy[i + 1] - dy[i]) * inv_h - dp[i - 1]) * rd;
        }
        M[n] = dp[n - 1];
#pragma unroll
        for (int i = n - 2; i >= 0; i--) M[i + 1] = dp[i] - cp[i] * M[i + 2];
    }

    constexpr float SIXTH = 1.0f / 6.0f;
#pragma unroll
    for (int i = 0; i < K - 1; i++) {
        sh_out[i] = make_float4(yv[i],
                                dy[i] - h * (2.0f * M[i] + M[i + 1]) * SIXTH,
                                0.5f * M[i],
                                (M[i + 1] - M[i]) * inv_h * SIXTH);
    }
}

// ===========================================================================
// Fast path kernel 1: per-edge precompute (u = r/|r|, f(|r|)). f-spline
// coefficients built per-block in registers -> shared.
// ===========================================================================
template <int K>
__global__ void __launch_bounds__(256) smeam_edge_kernel_ct(
    const float* __restrict__ r, const float* __restrict__ fy, int E) {
    __shared__ float4 sf[K - 1];
    if (threadIdx.x == 0) build_spline_reg<K>(fy, CUTOFF / (float)(K - 1), sf);
    __syncthreads();

    int i = blockIdx.x * blockDim.x + threadIdx.x;
    if (i >= E) return;
    float x = r[3 * i + 0];
    float y = r[3 * i + 1];
    float z = r[3 * i + 2];
    float d2 = x * x + y * y + z * z;
    float invl = rsqrtf(d2);
    float l = d2 * invl;

    constexpr float hf = CUTOFF / (float)(K - 1);
    constexpr float inv_hf = (float)(K - 1) / CUTOFF;
    int idx = min(max((int)(l * inv_hf), 0), K - 2);
    float s = l - (float)idx * hf;
    float4 cf = sf[idx];
    float fv = cf.x + s * (cf.y + s * (cf.z + s * cf.w));

    g_edge[i] = make_float4(x * invl, y * invl, z * invl, fv);
}

// ===========================================================================
// Fast path kernel 2: one warp handles U consecutive e2. Lane j handles
// partner e1 = src[e2]*deg + j (contiguous -> coalesced, L2-resident).
// g-spline coefficients built per-block -> shared.
// ===========================================================================
template <int K, int U>
__global__ void __launch_bounds__(256) smeam_main_kernel_ct(
    const int* __restrict__ src, const int* __restrict__ dst,
    const float* __restrict__ gy, float* __restrict__ out, int E) {
    __shared__ float4 sg[K - 1];
    __shared__ int sh_deg;
    if (threadIdx.x == 0) {
        build_spline_reg<K>(gy, 2.0f / (float)(K - 1), sg);
        int N = __ldg(&dst[E - 1]) + 1;
        sh_deg = E / N;
    }
    __syncthreads();

    int warp = (blockIdx.x * blockDim.x + threadIdx.x) >> 5;
    int lane = threadIdx.x & 31;
    int base = warp * U;
    if (base >= E) return;
    int deg = sh_deg;

    constexpr float hg = 2.0f / (float)(K - 1);
    constexpr float inv_hg = (float)(K - 1) * 0.5f;

    float4 u2[U];
    int s2[U], d2v[U];
#pragma unroll
    for (int k = 0; k < U; k++) {
        int e2 = min(base + k, E - 1);
        u2[k] = g_edge[e2];          // broadcast load
        s2[k] = __ldg(&src[e2]);
        d2v[k] = __ldg(&dst[e2]);
    }

    float acc[U];
#pragma unroll
    for (int k = 0; k < U; k++) acc[k] = 0.0f;

    for (int j = lane; j < deg; j += 32) {
        float4 u1[U];
        int s1[U];
#pragma unroll
        for (int k = 0; k < U; k++) {
            int e1 = s2[k] * deg + j;
            u1[k] = g_edge[e1];
            s1[k] = __ldg(&src[e1]);
        }
#pragma unroll
        for (int k = 0; k < U; k++) {
            float c = -(u1[k].x * u2[k].x + u1[k].y * u2[k].y + u1[k].z * u2[k].z);
            c = fminf(fmaxf(c, -1.0f), 1.0f);
            float xc = c + 1.0f;                           // knot t0 = -1
            int idx = min((int)(xc * inv_hg), K - 2);      // xc >= 0
            float s = xc - (float)idx * hg;
            float4 cf = sg[idx];
            float gv = cf.x + s * (cf.y + s * (cf.z + s * cf.w));
            float m = u1[k].w * u2[k].w * gv;
            acc[k] += (s1[k] != d2v[k]) ? m : 0.0f;
        }
    }

#pragma unroll
    for (int k = 0; k < U; k++) {
#pragma unroll
        for (int o = 16; o; o >>= 1) acc[k] += __shfl_down_sync(0xffffffffu, acc[k], o);
    }
    if (lane == 0) {
#pragma unroll
        for (int k = 0; k < U; k++)
            if (base + k < E) out[base + k] = acc[k];
    }
}

// ===========================================================================
// Generic-K fallback (runtime K) — round-1 style, never used for K in [3,9].
// ===========================================================================
__device__ void build_spline_rt(const float* y, int K, float h, float4* outc) {
    double dy[MAXK];
    for (int i = 0; i < K - 1; i++) dy[i] = ((double)y[i + 1] - (double)y[i]) / (double)h;
    int n = K - 2;
    double M[MAXK];
    for (int i = 0; i < K; i++) M[i] = 0.0;
    if (n > 0) {
        double cp[MAXK], dp[MAXK];
        double hh = (double)h;
        cp[0] = hh / (4.0 * hh);
        dp[0] = 6.0 * (dy[1] - dy[0]) / (4.0 * hh);
        for (int i = 1; i < n; i++) {
            double denom = 4.0 * hh - hh * cp[i - 1];
            cp[i] = hh / denom;
            dp[i] = (6.0 * (dy[i + 1] - dy[i]) - hh * dp[i - 1]) / denom;
        }
        double x = dp[n - 1];
        M[n] = x;
        for (int i = n - 2; i >= 0; i--) { x = dp[i] - cp[i] * x; M[i + 1] = x; }
    }
    for (int i = 0; i < K - 1; i++) {
        outc[i] = make_float4((float)y[i],
                              (float)(dy[i] - (double)h * (2.0 * M[i] + M[i + 1]) / 6.0),
                              (float)(M[i] / 2.0),
                              (float)((M[i + 1] - M[i]) / (6.0 * (double)h)));
    }
}

__global__ void smeam_build_kernel_rt(const float* fy, const float* gy,
                                      const int* dst, int E, int K) {
    int N = dst[E - 1] + 1;
    g_deg = E / N;
    build_spline_rt(fy, K, CUTOFF / (float)(K - 1), g_fc);
    build_spline_rt(gy, K, 2.0f / (float)(K - 1), g_gc);
}

__global__ void smeam_edge_kernel_rt(const float* __restrict__ r, int E, int K) {
    int i = blockIdx.x * blockDim.x + threadIdx.x;
    if (i >= E) return;
    float x = r[3 * i + 0], y = r[3 * i + 1], z = r[3 * i + 2];
    float d2 = x * x + y * y + z * z;
    float invl = rsqrtf(d2);
    float l = d2 * invl;
    float hf = CUTOFF / (float)(K - 1);
    float inv_hf = (float)(K - 1) / CUTOFF;
    int idx = min(max((int)floorf(l * inv_hf), 0), K - 2);
    float s = l - (float)idx * hf;
    float4 cf = g_fc[idx];
    g_edge[i] = make_float4(x * invl, y * invl, z * invl,
                            cf.x + s * (cf.y + s * (cf.z + s * cf.w)));
}

__global__ void smeam_main_kernel_rt(const int* __restrict__ src,
                                     const int* __restrict__ dst,
                                     float* __restrict__ out, int E, int K) {
    int warp = (blockIdx.x * blockDim.x + threadIdx.x) >> 5;
    int lane = threadIdx.x & 31;
    if (warp >= E) return;
    int e2 = warp;
    float4 u2 = g_edge[e2];
    int s2 = src[e2], d2 = dst[e2];
    int deg = g_deg;
    float hg = 2.0f / (float)(K - 1);
    float inv_hg = (float)(K - 1) * 0.5f;
    float acc = 0.0f;
    for (int j = lane; j < deg; j += 32) {
        int e1 = s2 * deg + j;
        float4 u1 = g_edge[e1];
        int s1 = src[e1];
        float c = -(u1.x * u2.x + u1.y * u2.y + u1.z * u2.z);
        c = fminf(fmaxf(c, -1.0f), 1.0f);
        float xc = c + 1.0f;
        int idx = min(max((int)floorf(xc * inv_hg), 0), K - 2);
        float s = xc - (float)idx * hg;
        float4 cf = g_gc[idx];
        float gv = cf.x + s * (cf.y + s * (cf.z + s * cf.w));
        acc += (s1 != d2) ? u1.w * u2.w * gv : 0.0f;
    }
#pragma unroll
    for (int o = 16; o; o >>= 1) acc += __shfl_down_sync(0xffffffffu, acc, o);
    if (lane == 0) out[e2] = acc;
}

// ===========================================================================
template <int K>
static void launch_ct(const float* r, const float* fy, const float* gy,
                      const int* src, const int* dst, float* out, int E) {
    constexpr int U = 4;  // e2 per warp
    int t = 256;
    smeam_edge_kernel_ct<K><<<(E + t - 1) / t, t>>>(r, fy, E);
    long warps = ((long)E + U - 1) / U;
    long threads = warps * 32;
    unsigned blocks = (unsigned)((threads + t - 1) / t);
    smeam_main_kernel_ct<K, U><<<blocks, t>>>(src, dst, gy, out, E);
}

extern "C" void kernel_launch(void* const* d_in, const int* in_sizes, int n_in,
                              void* d_out, int out_size) {
    const float* r   = (const float*)d_in[0];
    const float* fy  = (const float*)d_in[1];
    const float* gy  = (const float*)d_in[2];
    const int*   src = (const int*)d_in[3];
    const int*   dst = (const int*)d_in[4];
    float*       out = (float*)d_out;

    int E = in_sizes[3];
    int K = in_sizes[1];

    switch (K) {
        case 3: launch_ct<3>(r, fy, gy, src, dst, out, E); break;
        case 4: launch_ct<4>(r, fy, gy, src, dst, out, E); break;
        case 5: launch_ct<5>(r, fy, gy, src, dst, out, E); break;
        case 6: launch_ct<6>(r, fy, gy, src, dst, out, E); break;
        case 7: launch_ct<7>(r, fy, gy, src, dst, out, E); break;
        case 8: launch_ct<8>(r, fy, gy, src, dst, out, E); break;
        case 9: launch_ct<9>(r, fy, gy, src, dst, out, E); break;
        default: {
            smeam_build_kernel_rt<<<1, 1>>>(fy, gy, dst, E, K);
            int t = 256;
            smeam_edge_kernel_rt<<<(E + t - 1) / t, t>>>(r, E, K);
            long total = (long)E * 32;
            unsigned blocks = (unsigned)((total + t - 1) / t);
            smeam_main_kernel_rt<<<blocks, t>>>(src, dst, out, E, K);
            break;
        }
    }
}